// round 16
// baseline (speedup 1.0000x reference)
#include <cuda_runtime.h>
#include <cstdint>

// Problem constants
#define B_   4
#define T_   2048
#define D_   768
#define H_   12
#define DH_  64
#define M_   (B_ * T_)     // 8192 rows

// Scratch (allocation-free: __device__ globals)
__device__ float g_q[B_ * H_ * T_ * DH_];   // [B,H,T,Dh]
__device__ float g_k[B_ * H_ * T_ * DH_];
__device__ float g_v[B_ * H_ * T_ * DH_];
__device__ float g_y[B_ * T_ * D_];         // [B,T,D] attention output

__device__ __forceinline__ uint32_t tf32_rna(float x) {
    uint32_t y;
    asm("cvt.rna.tf32.f32 %0, %1;" : "=r"(y) : "f"(x));
    return y;
}

__device__ __forceinline__ float ex2f(float x) {
    float y;
    asm("ex2.approx.f32 %0, %1;" : "=f"(y) : "f"(x));
    return y;
}

__device__ __forceinline__ void mma_tf32(float d[4], const uint32_t a[4],
                                         const uint32_t b[2]) {
    asm volatile(
        "mma.sync.aligned.m16n8k8.row.col.f32.tf32.tf32.f32 "
        "{%0,%1,%2,%3}, {%4,%5,%6,%7}, {%8,%9}, {%0,%1,%2,%3};"
        : "+f"(d[0]), "+f"(d[1]), "+f"(d[2]), "+f"(d[3])
        : "r"(a[0]), "r"(a[1]), "r"(a[2]), "r"(a[3]), "r"(b[0]), "r"(b[1]));
}

// ---------------------------------------------------------------------------
// TF32 mma.sync GEMM v6: v1 structure VERBATIM (occ 1, fat 32-reg staging,
// whole-tile load/store, double buffer, one sync/iter, z-fused QKV) with
// ONLY the smem layout changed:
//   LDT=40 (≡8 mod 32); within each 8-k group, logical slot order
//   {k0,k4,k1,k5,k2,k6,k3,k7}, physically xor-4'd per row parity.
//   -> fragment pair (k=lc, k=lc+4) = ONE LDS.64 at word (2lc)^(4*(row&1));
//      half-warp covers all 16 even word-pairs: conflict-free.
//   -> stores: 2 STS.128 per (row, group); quarter-warp covers all 8
//      bank-quads: conflict-free.
// LDS.32 count per warp-iter: 96 -> 48 (as LDS.64). Arithmetic identical.
// mode 0: gridDim.z=3 fused QKV; mode 3: A=g_y, out=outext.
// ---------------------------------------------------------------------------
#define KC        32
#define LDT       40
#define TILE_W    (128 * LDT)             // 5120 words
#define BUF_W     (2 * TILE_W)
#define NITER     (D_ / KC)               // 24
#define GEMM_SMEM (2 * BUF_W * 4)         // 81920 B

__global__ __launch_bounds__(256, 1) void gemm_tf32(
    const float* __restrict__ Aext,
    const float* __restrict__ W0, const float* __restrict__ W1,
    const float* __restrict__ W2,
    const float* __restrict__ bias0, const float* __restrict__ bias1,
    const float* __restrict__ bias2,
    float* __restrict__ outext, int mode)
{
    extern __shared__ uint32_t sm[];

    const int tid  = threadIdx.x;
    const int wid  = tid >> 5;
    const int lane = tid & 31;
    const int lr   = lane >> 2;
    const int lc   = lane & 3;
    const int warp_m = wid >> 2;
    const int warp_n = wid & 3;
    const int m0 = blockIdx.y * 128;
    const int n0 = blockIdx.x * 128;
    const int z  = blockIdx.z;

    const float* W    = (z == 0) ? W0 : (z == 1) ? W1 : W2;
    const float* bias = (z == 0) ? bias0 : (z == 1) ? bias1 : bias2;
    const float* A    = (mode == 3) ? g_y : Aext;

    const float* Ap = A + (size_t)m0 * D_;
    const float* Wp = W + (size_t)n0 * D_;

    float d[4][4][4];
    #pragma unroll
    for (int mi = 0; mi < 4; mi++)
        #pragma unroll
        for (int ni = 0; ni < 4; ni++)
            #pragma unroll
            for (int r = 0; r < 4; r++) d[mi][ni][r] = 0.0f;

    // staging: 2 units of (row, 8-k group) per matrix = 4 float4 each
    float4 ra[4], rw[4];

    auto load_tile = [&](int it) {
        const int kk = it * KC;
        #pragma unroll
        for (int i = 0; i < 2; i++) {
            const int u   = tid + i * 256;      // 0..511 (row, group) units
            const int row = u >> 2;
            const int ch  = u & 3;
            const size_t goff = (size_t)row * D_ + kk + ch * 8;
            ra[2 * i]     = *(const float4*)(Ap + goff);
            ra[2 * i + 1] = *(const float4*)(Ap + goff + 4);
            rw[2 * i]     = *(const float4*)(Wp + goff);
            rw[2 * i + 1] = *(const float4*)(Wp + goff + 4);
        }
    };
    auto store_tile = [&](int b) {
        uint32_t* As = sm + b * BUF_W;
        uint32_t* Ws = As + TILE_W;
        #pragma unroll
        for (int i = 0; i < 2; i++) {
            const int u   = tid + i * 256;
            const int row = u >> 2;
            const int ch  = u & 3;
            const int x4  = (row & 1) * 4;
            uint32_t* pa = As + row * LDT + ch * 8;
            uint32_t* pw = Ws + row * LDT + ch * 8;
            float4 lo = ra[2 * i], hi = ra[2 * i + 1];
            *(uint4*)(pa + (0 ^ x4)) = make_uint4(tf32_rna(lo.x), tf32_rna(hi.x),
                                                  tf32_rna(lo.y), tf32_rna(hi.y));
            *(uint4*)(pa + (4 ^ x4)) = make_uint4(tf32_rna(lo.z), tf32_rna(hi.z),
                                                  tf32_rna(lo.w), tf32_rna(hi.w));
            lo = rw[2 * i]; hi = rw[2 * i + 1];
            *(uint4*)(pw + (0 ^ x4)) = make_uint4(tf32_rna(lo.x), tf32_rna(hi.x),
                                                  tf32_rna(lo.y), tf32_rna(hi.y));
            *(uint4*)(pw + (4 ^ x4)) = make_uint4(tf32_rna(lo.z), tf32_rna(hi.z),
                                                  tf32_rna(lo.w), tf32_rna(hi.w));
        }
    };

    load_tile(0);
    store_tile(0);
    __syncthreads();

    const int woff = (2 * lc) ^ (4 * (lr & 1));   // pair slot (row parity = lr&1)

    for (int it = 0; it < NITER; ++it) {
        const int cur = it & 1;
        if (it + 1 < NITER) load_tile(it + 1);

        const uint32_t* As = sm + cur * BUF_W;
        const uint32_t* Ws = As + TILE_W;

        #pragma unroll
        for (int kg = 0; kg < 4; kg++) {
            uint32_t a[4][4], b[4][2];
            #pragma unroll
            for (int mi = 0; mi < 4; mi++) {
                const int base = (warp_m * 64 + mi * 16 + lr) * LDT + kg * 8 + woff;
                uint2 p0 = *(const uint2*)(As + base);
                uint2 p1 = *(const uint2*)(As + base + 8 * LDT);
                a[mi][0] = p0.x; a[mi][1] = p1.x;
                a[mi][2] = p0.y; a[mi][3] = p1.y;
            }
            #pragma unroll
            for (int ni = 0; ni < 4; ni++) {
                uint2 pb = *(const uint2*)(Ws + (warp_n * 32 + ni * 8 + lr) * LDT
                                              + kg * 8 + woff);
                b[ni][0] = pb.x; b[ni][1] = pb.y;
            }
            #pragma unroll
            for (int mi = 0; mi < 4; mi++)
                #pragma unroll
                for (int ni = 0; ni < 4; ni++)
                    mma_tf32(d[mi][ni], a[mi], b[ni]);
        }

        if (it + 1 < NITER) store_tile(cur ^ 1);
        __syncthreads();
    }

    #pragma unroll
    for (int ni = 0; ni < 4; ni++) {
        const int c  = n0 + warp_n * 32 + ni * 8 + 2 * lc;
        const float b0 = __ldg(bias + c);
        const float b1 = __ldg(bias + c + 1);
        #pragma unroll
        for (int mi = 0; mi < 4; mi++) {
            #pragma unroll
            for (int half = 0; half < 2; half++) {
                const int m = m0 + warp_m * 64 + mi * 16 + half * 8 + lr;
                float2 r;
                r.x = d[mi][ni][half * 2 + 0] + b0;
                r.y = d[mi][ni][half * 2 + 1] + b1;
                float* op;
                if (mode == 3) {
                    op = outext + (size_t)m * D_ + c;
                } else {
                    const int bb = m / T_;
                    const int t  = m % T_;
                    const int h  = c / DH_;
                    const int dh = c % DH_;
                    float* base = (z == 0) ? g_q : (z == 1) ? g_k : g_v;
                    op = base + (((size_t)(bb * H_ + h)) * T_ + t) * DH_ + dh;
                }
                *(float2*)op = r;
            }
        }
    }
}

// ---------------------------------------------------------------------------
// Tensor-core causal flash attention v5 — EXACT R15 (best measured ~230 us).
// occ 1, double-buffered K/V, one sync/tile, fat staging. FROZEN.
// ---------------------------------------------------------------------------
#define FA_LD    72
#define FA_KS_W  (64 * FA_LD)
#define FA_BUF_W (2 * FA_KS_W)            // Ks + Vs per buffer
#define FA_SMEM  (2 * FA_BUF_W * 4)       // two buffers = 73728 B
#define CEXP     0.1803368801111244f      // 0.125 * log2(e)

__global__ __launch_bounds__(256, 1) void flash_attn_tc()
{
    extern __shared__ uint32_t fsm[];

    const int tid  = threadIdx.x;
    const int wid  = tid >> 5;
    const int lane = tid & 31;
    const int lr   = lane >> 2;
    const int lc   = lane & 3;

    const int bh = blockIdx.y;
    const int q0 = ((int)gridDim.x - 1 - (int)blockIdx.x) * 128;  // heavy first
    const int qr0 = q0 + wid * 16;
    const int r0 = qr0 + lr;
    const int r1 = r0 + 8;

    const float* Qb = g_q + (size_t)bh * T_ * DH_;
    const float* Kb = g_k + (size_t)bh * T_ * DH_;
    const float* Vb = g_v + (size_t)bh * T_ * DH_;

    uint32_t q[8][4];
    #pragma unroll
    for (int ks = 0; ks < 8; ks++) {
        q[ks][0] = tf32_rna(Qb[(size_t)r0 * DH_ + ks * 8 + lc]);
        q[ks][1] = tf32_rna(Qb[(size_t)r1 * DH_ + ks * 8 + lc]);
        q[ks][2] = tf32_rna(Qb[(size_t)r0 * DH_ + ks * 8 + lc + 4]);
        q[ks][3] = tf32_rna(Qb[(size_t)r1 * DH_ + ks * 8 + lc + 4]);
    }

    float O[8][4];
    #pragma unroll
    for (int ni = 0; ni < 8; ni++)
        #pragma unroll
        for (int r = 0; r < 4; r++) O[ni][r] = 0.0f;

    float m0r = -1e30f, m1r = -1e30f;
    float l0 = 0.0f, l1 = 0.0f;

    const int ntiles = (q0 + 128) / 64;   // >= 2
    float4 stK[4], stV[4];                // fat staging (32 regs)

    auto ldg_tile = [&](int t) {
        if (t < ntiles) {
            const float* Kg = Kb + (size_t)(t * 64) * DH_;
            const float* Vg = Vb + (size_t)(t * 64) * DH_;
            #pragma unroll
            for (int i = 0; i < 4; i++) {
                const int f = tid + i * 256;
                const size_t off = (size_t)(f >> 4) * DH_ + (f & 15) * 4;
                stK[i] = *(const float4*)(Kg + off);
                stV[i] = *(const float4*)(Vg + off);
            }
        }
    };
    auto sts_tile = [&](int t) {
        if (t < ntiles) {
            uint32_t* Ks = fsm + (t & 1) * FA_BUF_W;
            uint32_t* Vs = Ks + FA_KS_W;
            #pragma unroll
            for (int i = 0; i < 4; i++) {
                const int f   = tid + i * 256;
                const int row = f >> 4;
                const int c4  = f & 15;
                const int rowp = (row & 56) | (((row & 3) << 1) | ((row & 7) >> 2));
                uint32_t* kb = Ks + rowp * FA_LD + (c4 >> 1) * 8 + (c4 & 1);
                kb[0] = tf32_rna(stK[i].x);
                kb[2] = tf32_rna(stK[i].y);
                kb[4] = tf32_rna(stK[i].z);
                kb[6] = tf32_rna(stK[i].w);
                *(uint4*)(Vs + row * FA_LD + c4 * 4) =
                    make_uint4(tf32_rna(stV[i].x), tf32_rna(stV[i].y),
                               tf32_rna(stV[i].z), tf32_rna(stV[i].w));
            }
        }
    };

    ldg_tile(0);
    sts_tile(0);
    __syncthreads();

    for (int t = 0; t < ntiles; t++) {
        if (t + 1 < ntiles) ldg_tile(t + 1);

        const int j0 = t * 64;
        if (j0 <= qr0 + 15) {
            const uint32_t* Ks = fsm + (t & 1) * FA_BUF_W;
            const uint32_t* Vs = Ks + FA_KS_W;
            const uint32_t* vb0 = Vs + lc * FA_LD + lr;
            const uint32_t* vb1 = Vs + (lc + 4) * FA_LD + lr;

            float S[8][4];
            #pragma unroll
            for (int ni = 0; ni < 8; ni++) {
                S[ni][0] = S[ni][1] = S[ni][2] = S[ni][3] = 0.0f;
                #pragma unroll
                for (int ks = 0; ks < 8; ks++) {
                    uint2 bv = *(const uint2*)(Ks + (ni * 8 + lr) * FA_LD
                                                  + ks * 8 + 2 * lc);
                    uint32_t b2[2] = { bv.x, bv.y };
                    mma_tf32(S[ni], q[ks], b2);
                }
            }

            if (j0 + 63 > qr0) {
                #pragma unroll
                for (int ni = 0; ni < 8; ni++) {
                    const int ka = j0 + ni * 8 + lc;
                    const int kb2 = ka + 4;
                    if (ka  > r0) S[ni][0] = -1e30f;
                    if (kb2 > r0) S[ni][1] = -1e30f;
                    if (ka  > r1) S[ni][2] = -1e30f;
                    if (kb2 > r1) S[ni][3] = -1e30f;
                }
            }

            float m0n = m0r, m1n = m1r;
            #pragma unroll
            for (int ni = 0; ni < 8; ni++) {
                m0n = fmaxf(m0n, fmaxf(S[ni][0], S[ni][1]));
                m1n = fmaxf(m1n, fmaxf(S[ni][2], S[ni][3]));
            }
            m0n = fmaxf(m0n, __shfl_xor_sync(0xFFFFFFFFu, m0n, 1));
            m0n = fmaxf(m0n, __shfl_xor_sync(0xFFFFFFFFu, m0n, 2));
            m1n = fmaxf(m1n, __shfl_xor_sync(0xFFFFFFFFu, m1n, 1));
            m1n = fmaxf(m1n, __shfl_xor_sync(0xFFFFFFFFu, m1n, 2));

            const float sf0 = ex2f((m0r - m0n) * CEXP);
            const float sf1 = ex2f((m1r - m1n) * CEXP);
            m0r = m0n; m1r = m1n;
            l0 *= sf0; l1 *= sf1;
            #pragma unroll
            for (int ni = 0; ni < 8; ni++) {
                O[ni][0] *= sf0; O[ni][1] *= sf0;
                O[ni][2] *= sf1; O[ni][3] *= sf1;
            }

            const float mc0 = m0n * CEXP;
            const float mc1 = m1n * CEXP;
            #pragma unroll
            for (int ni = 0; ni < 8; ni++) {
                S[ni][0] = ex2f(fmaf(S[ni][0], CEXP, -mc0));
                S[ni][1] = ex2f(fmaf(S[ni][1], CEXP, -mc0));
                S[ni][2] = ex2f(fmaf(S[ni][2], CEXP, -mc1));
                S[ni][3] = ex2f(fmaf(S[ni][3], CEXP, -mc1));
                l0 += S[ni][0] + S[ni][1];
                l1 += S[ni][2] + S[ni][3];
            }

            #pragma unroll
            for (int ks = 0; ks < 8; ks++) {
                uint32_t a[4] = { tf32_rna(S[ks][0]), tf32_rna(S[ks][2]),
                                  tf32_rna(S[ks][1]), tf32_rna(S[ks][3]) };
                #pragma unroll
                for (int ni = 0; ni < 8; ni++) {
                    uint32_t b2[2] = { vb0[ks * 8 * FA_LD + ni * 8],
                                       vb1[ks * 8 * FA_LD + ni * 8] };
                    mma_tf32(O[ni], a, b2);
                }
            }
        }

        if (t + 1 < ntiles) sts_tile(t + 1);   // other buffer — safe pre-sync
        __syncthreads();
    }

    l0 += __shfl_xor_sync(0xFFFFFFFFu, l0, 1);
    l0 += __shfl_xor_sync(0xFFFFFFFFu, l0, 2);
    l1 += __shfl_xor_sync(0xFFFFFFFFu, l1, 1);
    l1 += __shfl_xor_sync(0xFFFFFFFFu, l1, 2);
    const float inv0 = 1.0f / l0;
    const float inv1 = 1.0f / l1;

    const int b = bh / H_;
    const int h = bh % H_;
    float* y0 = g_y + ((size_t)(b * T_ + r0)) * D_ + h * DH_;
    float* y1 = g_y + ((size_t)(b * T_ + r1)) * D_ + h * DH_;
    #pragma unroll
    for (int ni = 0; ni < 8; ni++) {
        *(float2*)(y0 + ni * 8 + 2 * lc) = make_float2(O[ni][0] * inv0, O[ni][1] * inv0);
        *(float2*)(y1 + ni * 8 + 2 * lc) = make_float2(O[ni][2] * inv1, O[ni][3] * inv1);
    }
}

// ---------------------------------------------------------------------------
// Launch. Inputs (metadata order): x, Wq, bq, Wk, bk, Wv, bv, Wp, bp
// ---------------------------------------------------------------------------
extern "C" void kernel_launch(void* const* d_in, const int* in_sizes, int n_in,
                              void* d_out, int out_size)
{
    (void)in_sizes; (void)n_in; (void)out_size;
    const float* x  = (const float*)d_in[0];
    const float* Wq = (const float*)d_in[1];
    const float* bq = (const float*)d_in[2];
    const float* Wk = (const float*)d_in[3];
    const float* bk = (const float*)d_in[4];
    const float* Wv = (const float*)d_in[5];
    const float* bv = (const float*)d_in[6];
    const float* Wp = (const float*)d_in[7];
    const float* bp = (const float*)d_in[8];
    float* out = (float*)d_out;

    cudaFuncSetAttribute(gemm_tf32, cudaFuncAttributeMaxDynamicSharedMemorySize,
                         GEMM_SMEM);
    cudaFuncSetAttribute(flash_attn_tc, cudaFuncAttributeMaxDynamicSharedMemorySize,
                         FA_SMEM);

    // fused Q/K/V projections: one launch, 1152 CTAs
    gemm_tf32<<<dim3(D_ / 128, M_ / 128, 3), 256, GEMM_SMEM>>>(
        x, Wq, Wk, Wv, bq, bk, bv, nullptr, 0);

    flash_attn_tc<<<dim3(T_ / 128, B_ * H_), 256, FA_SMEM>>>();

    // output projection
    gemm_tf32<<<dim3(D_ / 128, M_ / 128, 1), 256, GEMM_SMEM>>>(
        nullptr, Wp, Wp, Wp, bp, bp, bp, out, 3);
}

// round 17
// speedup vs baseline: 1.0827x; 1.0827x over previous
#include <cuda_runtime.h>
#include <cstdint>

// Problem constants
#define B_   4
#define T_   2048
#define D_   768
#define H_   12
#define DH_  64
#define M_   (B_ * T_)     // 8192 rows

// Scratch (allocation-free: __device__ globals)
__device__ float g_q[B_ * H_ * T_ * DH_];   // [B,H,T,Dh]
__device__ float g_k[B_ * H_ * T_ * DH_];
__device__ float g_v[B_ * H_ * T_ * DH_];
__device__ float g_y[B_ * T_ * D_];         // [B,T,D] attention output

__device__ __forceinline__ uint32_t tf32_rna(float x) {
    uint32_t y;
    asm("cvt.rna.tf32.f32 %0, %1;" : "=r"(y) : "f"(x));
    return y;
}

__device__ __forceinline__ float ex2f(float x) {
    float y;
    asm("ex2.approx.f32 %0, %1;" : "=f"(y) : "f"(x));
    return y;
}

__device__ __forceinline__ void mma_tf32(float d[4], const uint32_t a[4],
                                         const uint32_t b[2]) {
    asm volatile(
        "mma.sync.aligned.m16n8k8.row.col.f32.tf32.tf32.f32 "
        "{%0,%1,%2,%3}, {%4,%5,%6,%7}, {%8,%9}, {%0,%1,%2,%3};"
        : "+f"(d[0]), "+f"(d[1]), "+f"(d[2]), "+f"(d[3])
        : "r"(a[0]), "r"(a[1]), "r"(a[2]), "r"(a[3]), "r"(b[0]), "r"(b[1]));
}

// ---------------------------------------------------------------------------
// TF32 mma.sync GEMM — EXACT R15 v1 (best measured: QKV 230, proj 86).
// z-fused QKV (mode 0) / output projection (mode 3). 256 thr, tile 128x128,
// warp 64x32, KC=32 double-buffered, 1 CTA/SM, fat 32-reg staging, LDT=36.
// smem-layout variants (R9/R11/R16) all measured slower. FROZEN.
// ---------------------------------------------------------------------------
#define KC        32
#define LDT       36
#define TILE_W    (128 * LDT)
#define BUF_W     (2 * TILE_W)
#define NITER     (D_ / KC)
#define GEMM_SMEM (2 * BUF_W * 4)

__global__ __launch_bounds__(256, 1) void gemm_tf32(
    const float* __restrict__ Aext,
    const float* __restrict__ W0, const float* __restrict__ W1,
    const float* __restrict__ W2,
    const float* __restrict__ bias0, const float* __restrict__ bias1,
    const float* __restrict__ bias2,
    float* __restrict__ outext, int mode)
{
    extern __shared__ uint32_t sm[];

    const int tid  = threadIdx.x;
    const int wid  = tid >> 5;
    const int lane = tid & 31;
    const int lr   = lane >> 2;
    const int lc   = lane & 3;
    const int warp_m = wid >> 2;
    const int warp_n = wid & 3;
    const int m0 = blockIdx.y * 128;
    const int n0 = blockIdx.x * 128;
    const int z  = blockIdx.z;

    const float* W    = (z == 0) ? W0 : (z == 1) ? W1 : W2;
    const float* bias = (z == 0) ? bias0 : (z == 1) ? bias1 : bias2;
    const float* A    = (mode == 3) ? g_y : Aext;

    const float* Ap = A + (size_t)m0 * D_;
    const float* Wp = W + (size_t)n0 * D_;

    float d[4][4][4];
    #pragma unroll
    for (int mi = 0; mi < 4; mi++)
        #pragma unroll
        for (int ni = 0; ni < 4; ni++)
            #pragma unroll
            for (int r = 0; r < 4; r++) d[mi][ni][r] = 0.0f;

    float4 ra[4], rw[4];

    auto load_tile = [&](int it) {
        const int kk = it * KC;
        #pragma unroll
        for (int i = 0; i < 4; i++) {
            const int f   = tid + i * 256;
            const int row = f >> 3;
            const int c4  = f & 7;
            const size_t goff = (size_t)row * D_ + kk + c4 * 4;
            ra[i] = *(const float4*)(Ap + goff);
            rw[i] = *(const float4*)(Wp + goff);
        }
    };
    auto store_tile = [&](int b) {
        uint32_t* As = sm + b * BUF_W;
        uint32_t* Ws = As + TILE_W;
        #pragma unroll
        for (int i = 0; i < 4; i++) {
            const int f   = tid + i * 256;
            const int row = f >> 3;
            const int c4  = f & 7;
            const int off = row * LDT + c4 * 4;
            uint32_t a0 = tf32_rna(ra[i].x), a1 = tf32_rna(ra[i].y),
                     a2 = tf32_rna(ra[i].z), a3 = tf32_rna(ra[i].w);
            uint32_t w0 = tf32_rna(rw[i].x), w1 = tf32_rna(rw[i].y),
                     w2 = tf32_rna(rw[i].z), w3 = tf32_rna(rw[i].w);
            *(uint4*)(As + off) = make_uint4(a0, a1, a2, a3);
            *(uint4*)(Ws + off) = make_uint4(w0, w1, w2, w3);
        }
    };

    load_tile(0);
    store_tile(0);
    __syncthreads();

    for (int it = 0; it < NITER; ++it) {
        const int cur = it & 1;
        if (it + 1 < NITER) load_tile(it + 1);

        const uint32_t* As = sm + cur * BUF_W;
        const uint32_t* Ws = As + TILE_W;

        #pragma unroll
        for (int k0 = 0; k0 < KC; k0 += 8) {
            uint32_t a[4][4], b[4][2];
            #pragma unroll
            for (int mi = 0; mi < 4; mi++) {
                const int r = warp_m * 64 + mi * 16;
                a[mi][0] = As[(r + lr)     * LDT + k0 + lc];
                a[mi][1] = As[(r + 8 + lr) * LDT + k0 + lc];
                a[mi][2] = As[(r + lr)     * LDT + k0 + 4 + lc];
                a[mi][3] = As[(r + 8 + lr) * LDT + k0 + 4 + lc];
            }
            #pragma unroll
            for (int ni = 0; ni < 4; ni++) {
                const int n = warp_n * 32 + ni * 8;
                b[ni][0] = Ws[(n + lr) * LDT + k0 + lc];
                b[ni][1] = Ws[(n + lr) * LDT + k0 + 4 + lc];
            }
            #pragma unroll
            for (int mi = 0; mi < 4; mi++)
                #pragma unroll
                for (int ni = 0; ni < 4; ni++)
                    mma_tf32(d[mi][ni], a[mi], b[ni]);
        }

        if (it + 1 < NITER) store_tile(cur ^ 1);
        __syncthreads();
    }

    #pragma unroll
    for (int ni = 0; ni < 4; ni++) {
        const int c  = n0 + warp_n * 32 + ni * 8 + 2 * lc;
        const float b0 = __ldg(bias + c);
        const float b1 = __ldg(bias + c + 1);
        #pragma unroll
        for (int mi = 0; mi < 4; mi++) {
            #pragma unroll
            for (int half = 0; half < 2; half++) {
                const int m = m0 + warp_m * 64 + mi * 16 + half * 8 + lr;
                float2 r;
                r.x = d[mi][ni][half * 2 + 0] + b0;
                r.y = d[mi][ni][half * 2 + 1] + b1;
                float* op;
                if (mode == 3) {
                    op = outext + (size_t)m * D_ + c;
                } else {
                    const int bb = m / T_;
                    const int t  = m % T_;
                    const int h  = c / DH_;
                    const int dh = c % DH_;
                    float* base = (z == 0) ? g_q : (z == 1) ? g_k : g_v;
                    op = base + (((size_t)(bb * H_ + h)) * T_ + t) * DH_ + dh;
                }
                *(float2*)op = r;
            }
        }
    }
}

// ---------------------------------------------------------------------------
// Tensor-core causal flash attention v5 (R15, best measured ~230 us) with
// one change: PV A-fragments pass RAW fp32 bit-patterns (HW tf32 truncation,
// cutlass fast-tf32 input path) instead of cvt.rna — removes 32 CVT per
// tile per warp. Everything else frozen.
// ---------------------------------------------------------------------------
#define FA_LD    72
#define FA_KS_W  (64 * FA_LD)
#define FA_BUF_W (2 * FA_KS_W)            // Ks + Vs per buffer
#define FA_SMEM  (2 * FA_BUF_W * 4)       // two buffers = 73728 B
#define CEXP     0.1803368801111244f      // 0.125 * log2(e)

__global__ __launch_bounds__(256, 1) void flash_attn_tc()
{
    extern __shared__ uint32_t fsm[];

    const int tid  = threadIdx.x;
    const int wid  = tid >> 5;
    const int lane = tid & 31;
    const int lr   = lane >> 2;
    const int lc   = lane & 3;

    const int bh = blockIdx.y;
    const int q0 = ((int)gridDim.x - 1 - (int)blockIdx.x) * 128;  // heavy first
    const int qr0 = q0 + wid * 16;
    const int r0 = qr0 + lr;
    const int r1 = r0 + 8;

    const float* Qb = g_q + (size_t)bh * T_ * DH_;
    const float* Kb = g_k + (size_t)bh * T_ * DH_;
    const float* Vb = g_v + (size_t)bh * T_ * DH_;

    uint32_t q[8][4];
    #pragma unroll
    for (int ks = 0; ks < 8; ks++) {
        q[ks][0] = tf32_rna(Qb[(size_t)r0 * DH_ + ks * 8 + lc]);
        q[ks][1] = tf32_rna(Qb[(size_t)r1 * DH_ + ks * 8 + lc]);
        q[ks][2] = tf32_rna(Qb[(size_t)r0 * DH_ + ks * 8 + lc + 4]);
        q[ks][3] = tf32_rna(Qb[(size_t)r1 * DH_ + ks * 8 + lc + 4]);
    }

    float O[8][4];
    #pragma unroll
    for (int ni = 0; ni < 8; ni++)
        #pragma unroll
        for (int r = 0; r < 4; r++) O[ni][r] = 0.0f;

    float m0r = -1e30f, m1r = -1e30f;
    float l0 = 0.0f, l1 = 0.0f;

    const int ntiles = (q0 + 128) / 64;   // >= 2
    float4 stK[4], stV[4];                // fat staging (32 regs)

    auto ldg_tile = [&](int t) {
        if (t < ntiles) {
            const float* Kg = Kb + (size_t)(t * 64) * DH_;
            const float* Vg = Vb + (size_t)(t * 64) * DH_;
            #pragma unroll
            for (int i = 0; i < 4; i++) {
                const int f = tid + i * 256;
                const size_t off = (size_t)(f >> 4) * DH_ + (f & 15) * 4;
                stK[i] = *(const float4*)(Kg + off);
                stV[i] = *(const float4*)(Vg + off);
            }
        }
    };
    auto sts_tile = [&](int t) {
        if (t < ntiles) {
            uint32_t* Ks = fsm + (t & 1) * FA_BUF_W;
            uint32_t* Vs = Ks + FA_KS_W;
            #pragma unroll
            for (int i = 0; i < 4; i++) {
                const int f   = tid + i * 256;
                const int row = f >> 4;
                const int c4  = f & 15;
                const int rowp = (row & 56) | (((row & 3) << 1) | ((row & 7) >> 2));
                uint32_t* kb = Ks + rowp * FA_LD + (c4 >> 1) * 8 + (c4 & 1);
                kb[0] = tf32_rna(stK[i].x);
                kb[2] = tf32_rna(stK[i].y);
                kb[4] = tf32_rna(stK[i].z);
                kb[6] = tf32_rna(stK[i].w);
                *(uint4*)(Vs + row * FA_LD + c4 * 4) =
                    make_uint4(tf32_rna(stV[i].x), tf32_rna(stV[i].y),
                               tf32_rna(stV[i].z), tf32_rna(stV[i].w));
            }
        }
    };

    ldg_tile(0);
    sts_tile(0);
    __syncthreads();

    for (int t = 0; t < ntiles; t++) {
        if (t + 1 < ntiles) ldg_tile(t + 1);

        const int j0 = t * 64;
        if (j0 <= qr0 + 15) {
            const uint32_t* Ks = fsm + (t & 1) * FA_BUF_W;
            const uint32_t* Vs = Ks + FA_KS_W;
            const uint32_t* vb0 = Vs + lc * FA_LD + lr;
            const uint32_t* vb1 = Vs + (lc + 4) * FA_LD + lr;

            float S[8][4];
            #pragma unroll
            for (int ni = 0; ni < 8; ni++) {
                S[ni][0] = S[ni][1] = S[ni][2] = S[ni][3] = 0.0f;
                #pragma unroll
                for (int ks = 0; ks < 8; ks++) {
                    uint2 bv = *(const uint2*)(Ks + (ni * 8 + lr) * FA_LD
                                                  + ks * 8 + 2 * lc);
                    uint32_t b2[2] = { bv.x, bv.y };
                    mma_tf32(S[ni], q[ks], b2);
                }
            }

            if (j0 + 63 > qr0) {
                #pragma unroll
                for (int ni = 0; ni < 8; ni++) {
                    const int ka = j0 + ni * 8 + lc;
                    const int kb2 = ka + 4;
                    if (ka  > r0) S[ni][0] = -1e30f;
                    if (kb2 > r0) S[ni][1] = -1e30f;
                    if (ka  > r1) S[ni][2] = -1e30f;
                    if (kb2 > r1) S[ni][3] = -1e30f;
                }
            }

            float m0n = m0r, m1n = m1r;
            #pragma unroll
            for (int ni = 0; ni < 8; ni++) {
                m0n = fmaxf(m0n, fmaxf(S[ni][0], S[ni][1]));
                m1n = fmaxf(m1n, fmaxf(S[ni][2], S[ni][3]));
            }
            m0n = fmaxf(m0n, __shfl_xor_sync(0xFFFFFFFFu, m0n, 1));
            m0n = fmaxf(m0n, __shfl_xor_sync(0xFFFFFFFFu, m0n, 2));
            m1n = fmaxf(m1n, __shfl_xor_sync(0xFFFFFFFFu, m1n, 1));
            m1n = fmaxf(m1n, __shfl_xor_sync(0xFFFFFFFFu, m1n, 2));

            const float sf0 = ex2f((m0r - m0n) * CEXP);
            const float sf1 = ex2f((m1r - m1n) * CEXP);
            m0r = m0n; m1r = m1n;
            l0 *= sf0; l1 *= sf1;
            #pragma unroll
            for (int ni = 0; ni < 8; ni++) {
                O[ni][0] *= sf0; O[ni][1] *= sf0;
                O[ni][2] *= sf1; O[ni][3] *= sf1;
            }

            const float mc0 = m0n * CEXP;
            const float mc1 = m1n * CEXP;
            #pragma unroll
            for (int ni = 0; ni < 8; ni++) {
                S[ni][0] = ex2f(fmaf(S[ni][0], CEXP, -mc0));
                S[ni][1] = ex2f(fmaf(S[ni][1], CEXP, -mc0));
                S[ni][2] = ex2f(fmaf(S[ni][2], CEXP, -mc1));
                S[ni][3] = ex2f(fmaf(S[ni][3], CEXP, -mc1));
                l0 += S[ni][0] + S[ni][1];
                l1 += S[ni][2] + S[ni][3];
            }

            // ---- O += P @ V : A-frag = {c0,c2,c1,c3} of S ----
            // raw fp32 bits: tf32 HMMA truncates low mantissa (fast-tf32 path)
            #pragma unroll
            for (int ks = 0; ks < 8; ks++) {
                uint32_t a[4] = { __float_as_uint(S[ks][0]),
                                  __float_as_uint(S[ks][2]),
                                  __float_as_uint(S[ks][1]),
                                  __float_as_uint(S[ks][3]) };
                #pragma unroll
                for (int ni = 0; ni < 8; ni++) {
                    uint32_t b2[2] = { vb0[ks * 8 * FA_LD + ni * 8],
                                       vb1[ks * 8 * FA_LD + ni * 8] };
                    mma_tf32(O[ni], a, b2);
                }
            }
        }

        if (t + 1 < ntiles) sts_tile(t + 1);   // other buffer — safe pre-sync
        __syncthreads();
    }

    l0 += __shfl_xor_sync(0xFFFFFFFFu, l0, 1);
    l0 += __shfl_xor_sync(0xFFFFFFFFu, l0, 2);
    l1 += __shfl_xor_sync(0xFFFFFFFFu, l1, 1);
    l1 += __shfl_xor_sync(0xFFFFFFFFu, l1, 2);
    const float inv0 = 1.0f / l0;
    const float inv1 = 1.0f / l1;

    const int b = bh / H_;
    const int h = bh % H_;
    float* y0 = g_y + ((size_t)(b * T_ + r0)) * D_ + h * DH_;
    float* y1 = g_y + ((size_t)(b * T_ + r1)) * D_ + h * DH_;
    #pragma unroll
    for (int ni = 0; ni < 8; ni++) {
        *(float2*)(y0 + ni * 8 + 2 * lc) = make_float2(O[ni][0] * inv0, O[ni][1] * inv0);
        *(float2*)(y1 + ni * 8 + 2 * lc) = make_float2(O[ni][2] * inv1, O[ni][3] * inv1);
    }
}

// ---------------------------------------------------------------------------
// Launch. Inputs (metadata order): x, Wq, bq, Wk, bk, Wv, bv, Wp, bp
// ---------------------------------------------------------------------------
extern "C" void kernel_launch(void* const* d_in, const int* in_sizes, int n_in,
                              void* d_out, int out_size)
{
    (void)in_sizes; (void)n_in; (void)out_size;
    const float* x  = (const float*)d_in[0];
    const float* Wq = (const float*)d_in[1];
    const float* bq = (const float*)d_in[2];
    const float* Wk = (const float*)d_in[3];
    const float* bk = (const float*)d_in[4];
    const float* Wv = (const float*)d_in[5];
    const float* bv = (const float*)d_in[6];
    const float* Wp = (const float*)d_in[7];
    const float* bp = (const float*)d_in[8];
    float* out = (float*)d_out;

    cudaFuncSetAttribute(gemm_tf32, cudaFuncAttributeMaxDynamicSharedMemorySize,
                         GEMM_SMEM);
    cudaFuncSetAttribute(flash_attn_tc, cudaFuncAttributeMaxDynamicSharedMemorySize,
                         FA_SMEM);

    // fused Q/K/V projections: one launch, 1152 CTAs
    gemm_tf32<<<dim3(D_ / 128, M_ / 128, 3), 256, GEMM_SMEM>>>(
        x, Wq, Wk, Wv, bq, bk, bv, nullptr, 0);

    flash_attn_tc<<<dim3(T_ / 128, B_ * H_), 256, FA_SMEM>>>();

    // output projection
    gemm_tf32<<<dim3(D_ / 128, M_ / 128, 1), 256, GEMM_SMEM>>>(
        nullptr, Wp, Wp, Wp, bp, bp, bp, out, 3);
}